// round 1
// baseline (speedup 1.0000x reference)
#include <cuda_runtime.h>
#include <cstdint>

// ---------------- device scratch (no allocations allowed) ----------------
__device__ unsigned int d_hist255[256];
__device__ unsigned int d_hist1[256];
__device__ unsigned int d_maxbits;          // float-as-bits, inputs >= 0
__device__ float d_alpha_eff, d_beta_eff, d_hi;
__device__ int   d_identity;

// ---------------- init ----------------
__global__ void k_init() {
    int t = threadIdx.x;
    d_hist255[t] = 0u;
    d_hist1[t]   = 0u;
    if (t == 0) d_maxbits = 0u;
}

// ---------------- pass 1: global max + scale=255 histogram ----------------
__global__ __launch_bounds__(256) void k_pass1(const float* __restrict__ img, int npix4) {
    __shared__ unsigned int sh[256];
    __shared__ unsigned int smax;
    int t = threadIdx.x;
    sh[t] = 0u;
    if (t == 0) smax = 0u;
    __syncthreads();

    const float4* p0 = (const float4*)img;
    const float4* p1 = p0 + npix4;
    const float4* p2 = p1 + npix4;

    float lmax = 0.0f;
    int stride = gridDim.x * blockDim.x;
    for (int i = blockIdx.x * blockDim.x + t; i < npix4; i += stride) {
        float4 a = __ldg(p0 + i);
        float4 b = __ldg(p1 + i);
        float4 c = __ldg(p2 + i);

        float am = fmaxf(fmaxf(a.x, a.y), fmaxf(a.z, a.w));
        float bm = fmaxf(fmaxf(b.x, b.y), fmaxf(b.z, b.w));
        float cm = fmaxf(fmaxf(c.x, c.y), fmaxf(c.z, c.w));
        lmax = fmaxf(lmax, fmaxf(am, fmaxf(bm, cm)));

        float ax[4] = {a.x, a.y, a.z, a.w};
        float bx[4] = {b.x, b.y, b.z, b.w};
        float cx[4] = {c.x, c.y, c.z, c.w};
        #pragma unroll
        for (int k = 0; k < 4; k++) {
            // mirror reference: scale to [0,255] first, then weighted gray
            float g = 0.299f * (ax[k] * 255.0f)
                    + 0.587f * (bx[k] * 255.0f)
                    + 0.114f * (cx[k] * 255.0f);
            if (g >= 0.0f && g <= 255.0f) {
                int idx = (int)(g * (256.0f / 255.0f));   // floor for g>=0
                idx = min(idx, 255);
                atomicAdd(&sh[idx], 1u);
            }
        }
    }

    // warp-reduce max, then block, then one global atomicMax
    #pragma unroll
    for (int off = 16; off > 0; off >>= 1)
        lmax = fmaxf(lmax, __shfl_xor_sync(0xFFFFFFFFu, lmax, off));
    if ((t & 31) == 0)
        atomicMax(&smax, __float_as_uint(lmax));
    __syncthreads();
    if (t == 0)
        atomicMax(&d_maxbits, smax);

    unsigned int h = sh[t];
    if (h) atomicAdd(&d_hist255[t], h);
}

// ---------------- pass 1b: scale=1 histogram, only if NOT normalized ----------------
__global__ __launch_bounds__(256) void k_pass1b(const float* __restrict__ img, int npix4) {
    // uniform-read flag; whole block exits if input is normalized (max <= 1)
    if (__uint_as_float(d_maxbits) <= 1.0f) return;

    __shared__ unsigned int sh[256];
    int t = threadIdx.x;
    sh[t] = 0u;
    __syncthreads();

    const float4* p0 = (const float4*)img;
    const float4* p1 = p0 + npix4;
    const float4* p2 = p1 + npix4;

    int stride = gridDim.x * blockDim.x;
    for (int i = blockIdx.x * blockDim.x + t; i < npix4; i += stride) {
        float4 a = __ldg(p0 + i);
        float4 b = __ldg(p1 + i);
        float4 c = __ldg(p2 + i);
        float ax[4] = {a.x, a.y, a.z, a.w};
        float bx[4] = {b.x, b.y, b.z, b.w};
        float cx[4] = {c.x, c.y, c.z, c.w};
        #pragma unroll
        for (int k = 0; k < 4; k++) {
            float g = 0.299f * ax[k] + 0.587f * bx[k] + 0.114f * cx[k];
            if (g >= 0.0f && g <= 255.0f) {
                int idx = (int)(g * (256.0f / 255.0f));
                idx = min(idx, 255);
                atomicAdd(&sh[idx], 1u);
            }
        }
    }
    __syncthreads();
    unsigned int h = sh[t];
    if (h) atomicAdd(&d_hist1[t], h);
}

// ---------------- stats: cumsum + thresholds -> affine params ----------------
__global__ void k_stats() {
    __shared__ float acc[256];
    __shared__ unsigned int cnt_lo, cnt_hi;
    int t = threadIdx.x;

    float maxv = __uint_as_float(d_maxbits);
    bool is_norm = (maxv <= 1.0f);
    unsigned int h = is_norm ? d_hist255[t] : d_hist1[t];
    acc[t] = (float)h;
    if (t == 0) { cnt_lo = 0u; cnt_hi = 0u; }
    __syncthreads();

    if (t == 0) {
        float s = 0.0f;
        for (int i = 0; i < 256; i++) { s += acc[i]; acc[i] = s; }
    }
    __syncthreads();

    float maximum = acc[255];
    float clip_value = (maximum / 100.0f) * 0.5f;   // CLIP_HIST_PERCENT = 1.0

    if (acc[t] < clip_value)              atomicAdd(&cnt_lo, 1u);
    if (acc[t] < (maximum - clip_value))  atomicAdd(&cnt_hi, 1u);
    __syncthreads();

    if (t == 0) {
        int min_gray = (int)cnt_lo;
        int max_gray = (int)cnt_hi - 1;
        float span = fmaxf((float)(max_gray - min_gray), 1.0f);
        float alpha = 255.0f / span;
        float beta  = -(float)min_gray * alpha;
        float scale = is_norm ? 255.0f : 1.0f;
        d_alpha_eff = alpha / scale;
        d_beta_eff  = beta / scale;
        d_hi        = is_norm ? 1.0f : 255.0f;
        d_identity  = (max_gray > min_gray) ? 0 : 1;
    }
}

// ---------------- apply: out = identity ? in : clamp(in*a+b, 0, hi) ----------------
__global__ __launch_bounds__(256) void k_apply(const float* __restrict__ in,
                                               float* __restrict__ out, int n4) {
    float a  = d_alpha_eff;
    float b  = d_beta_eff;
    float hi = d_hi;
    int   id = d_identity;

    const float4* pin  = (const float4*)in;
    float4*       pout = (float4*)out;
    int stride = gridDim.x * blockDim.x;
    for (int i = blockIdx.x * blockDim.x + threadIdx.x; i < n4; i += stride) {
        float4 v = __ldg(pin + i);
        float4 r;
        r.x = fminf(fmaxf(fmaf(v.x, a, b), 0.0f), hi);
        r.y = fminf(fmaxf(fmaf(v.y, a, b), 0.0f), hi);
        r.z = fminf(fmaxf(fmaf(v.z, a, b), 0.0f), hi);
        r.w = fminf(fmaxf(fmaf(v.w, a, b), 0.0f), hi);
        pout[i] = id ? v : r;
    }
}

// ---------------- entry ----------------
extern "C" void kernel_launch(void* const* d_in, const int* in_sizes, int n_in,
                              void* d_out, int out_size) {
    const float* img = (const float*)d_in[0];
    float* out = (float*)d_out;

    int n    = in_sizes[0];       // 3 * 4096 * 4096
    int npix = n / 3;             // 16777216
    int npix4 = npix / 4;         // 4194304 (npix divisible by 4)
    int n4    = n / 4;            // 12582912

    const int BLK = 256;
    const int GRID = 1184;        // ~8 blocks/SM on 148 SMs

    k_init<<<1, 256>>>();
    k_pass1<<<GRID, BLK>>>(img, npix4);
    k_pass1b<<<GRID, BLK>>>(img, npix4);
    k_stats<<<1, 256>>>();
    k_apply<<<GRID, BLK>>>(img, out, n4);
}

// round 2
// speedup vs baseline: 1.0019x; 1.0019x over previous
#include <cuda_runtime.h>

#define NB 256

// ---------------- device state (zero-initialized at module load; the stats
// block re-zeros everything at the end of each launch so graph replays see
// clean state; g_gen is monotonically increasing by design) ----------------
__device__ unsigned int g_hist255[NB];
__device__ unsigned int g_hist1[NB];
__device__ unsigned int g_maxbits;
__device__ unsigned int g_done1;
__device__ unsigned int g_done2;
__device__ unsigned int g_gen;
__device__ float g_alpha, g_beta, g_hi;
__device__ int   g_identity;

// ---------------- stats: parallel scan + thresholds + param write + cleanup.
// Executed by exactly ONE block (all 256 threads). Exact: all cumsum values
// are integers < 2^24, representable in fp32 regardless of summation order.
__device__ __forceinline__ void compute_stats(const unsigned int* hist,
                                              bool is_norm, int t,
                                              float* s_wsum, unsigned int* s_cnt)
{
    float x = (float)__ldcg(&hist[t]);
    #pragma unroll
    for (int off = 1; off < 32; off <<= 1) {
        float y = __shfl_up_sync(0xFFFFFFFFu, x, off);
        if ((t & 31) >= off) x += y;
    }
    if ((t & 31) == 31) s_wsum[t >> 5] = x;
    if (t < 2) s_cnt[t] = 0u;
    __syncthreads();
    if (t < 8) {
        float s = s_wsum[t];
        #pragma unroll
        for (int off = 1; off < 8; off <<= 1) {
            float y = __shfl_up_sync(0xFFu, s, off);
            if (t >= off) s += y;
        }
        s_wsum[t] = s;
    }
    __syncthreads();
    float acc = x + ((t >= 32) ? s_wsum[(t >> 5) - 1] : 0.0f);
    float maximum = s_wsum[7];
    float clip = (maximum / 100.0f) * 0.5f;   // CLIP_HIST_PERCENT = 1.0

    unsigned int bl = __ballot_sync(0xFFFFFFFFu, acc < clip);
    unsigned int bh = __ballot_sync(0xFFFFFFFFu, acc < (maximum - clip));
    if ((t & 31) == 0) {
        atomicAdd(&s_cnt[0], (unsigned)__popc(bl));
        atomicAdd(&s_cnt[1], (unsigned)__popc(bh));
    }
    // per-thread cleanup for next graph replay
    g_hist255[t] = 0u;
    g_hist1[t]   = 0u;
    __syncthreads();
    if (t == 0) {
        int min_gray = (int)s_cnt[0];
        int max_gray = (int)s_cnt[1] - 1;
        float span  = fmaxf((float)(max_gray - min_gray), 1.0f);
        float alpha = 255.0f / span;
        float beta  = -(float)min_gray * alpha;
        float scale = is_norm ? 255.0f : 1.0f;
        g_alpha = alpha / scale;
        g_beta  = beta / scale;
        g_hi    = is_norm ? 1.0f : 255.0f;
        g_identity = (max_gray > min_gray) ? 0 : 1;
        g_maxbits = 0u; g_done1 = 0u; g_done2 = 0u;
    }
    __syncthreads();
}

__device__ __forceinline__ void hist_pixel(float g, unsigned int* sh)
{
    if (g >= 0.0f && g <= 255.0f) {
        int idx = (int)(g * (256.0f / 255.0f));   // floor for g >= 0
        idx = min(idx, 255);
        atomicAdd(&sh[idx], 1u);
    }
}

// ---------------- the one persistent fused kernel ----------------
__global__ __launch_bounds__(256)
void k_fused(const float* __restrict__ img, float* __restrict__ out,
             int npix4, int n4)
{
    __shared__ unsigned int sh[NB];
    __shared__ unsigned int smax;
    __shared__ unsigned int s_flag;
    __shared__ unsigned int s_g0;
    __shared__ float        s_wsum[8];
    __shared__ unsigned int s_cnt[2];

    const int t = threadIdx.x;
    const int G = gridDim.x;
    const int stride = G * 256;

    if (t == 0) {
        s_g0 = *(volatile unsigned int*)&g_gen;
        smax = 0u;
    }
    sh[t] = 0u;
    __syncthreads();
    const unsigned int g0 = s_g0;

    const float4* p0 = (const float4*)img;
    const float4* p1 = p0 + npix4;
    const float4* p2 = p1 + npix4;

    // ---- phase 1: global max + scale=255 histogram (one read of image) ----
    float lmax = 0.0f;
    for (int i = blockIdx.x * 256 + t; i < npix4; i += stride) {
        float4 a = __ldcs(p0 + i);
        float4 b = __ldcs(p1 + i);
        float4 c = __ldcs(p2 + i);

        float am = fmaxf(fmaxf(a.x, a.y), fmaxf(a.z, a.w));
        float bm = fmaxf(fmaxf(b.x, b.y), fmaxf(b.z, b.w));
        float cm = fmaxf(fmaxf(c.x, c.y), fmaxf(c.z, c.w));
        lmax = fmaxf(lmax, fmaxf(am, fmaxf(bm, cm)));

        hist_pixel(0.299f*(a.x*255.0f) + 0.587f*(b.x*255.0f) + 0.114f*(c.x*255.0f), sh);
        hist_pixel(0.299f*(a.y*255.0f) + 0.587f*(b.y*255.0f) + 0.114f*(c.y*255.0f), sh);
        hist_pixel(0.299f*(a.z*255.0f) + 0.587f*(b.z*255.0f) + 0.114f*(c.z*255.0f), sh);
        hist_pixel(0.299f*(a.w*255.0f) + 0.587f*(b.w*255.0f) + 0.114f*(c.w*255.0f), sh);
    }

    #pragma unroll
    for (int off = 16; off > 0; off >>= 1)
        lmax = fmaxf(lmax, __shfl_xor_sync(0xFFFFFFFFu, lmax, off));
    if ((t & 31) == 0) atomicMax(&smax, __float_as_uint(lmax));
    __syncthreads();
    if (t == 0) atomicMax(&g_maxbits, smax);

    { unsigned int h = sh[t]; if (h) atomicAdd(&g_hist255[t], h); }
    __threadfence();
    __syncthreads();

    // ---- barrier A: last-arriving block decides + (maybe) computes stats ----
    if (t == 0) {
        unsigned int old = atomicAdd(&g_done1, 1u);
        s_flag = (old == (unsigned)(G - 1)) ? 1u : 0u;
    }
    __syncthreads();
    bool last1 = (s_flag != 0u);
    int d;  // generation delta observed: 1 = do hist1 pass, 2 = params ready

    if (last1) {
        __threadfence();
        if (t == 0) {
            unsigned int mb = atomicMax(&g_maxbits, 0u);  // read current value
            s_flag = (__uint_as_float(mb) <= 1.0f) ? 1u : 0u;
        }
        __syncthreads();
        bool is_norm = (s_flag != 0u);
        __syncthreads();
        if (is_norm) {
            compute_stats(g_hist255, true, t, s_wsum, s_cnt);
            if (t == 0) { __threadfence(); atomicAdd(&g_gen, 2u); }
            d = 2;
        } else {
            if (t == 0) { __threadfence(); atomicAdd(&g_gen, 1u); }
            d = 1;
        }
    } else {
        if (t == 0) {
            unsigned int g;
            do { g = *(volatile unsigned int*)&g_gen; __nanosleep(32); } while (g == g0);
            s_flag = g - g0;
        }
        __syncthreads();
        d = (int)s_flag;
    }

    // ---- optional phase 1b: scale=1 histogram (only when input NOT normalized) ----
    if (d == 1) {
        __syncthreads();
        sh[t] = 0u;
        __syncthreads();
        for (int i = blockIdx.x * 256 + t; i < npix4; i += stride) {
            float4 a = __ldcs(p0 + i);
            float4 b = __ldcs(p1 + i);
            float4 c = __ldcs(p2 + i);
            hist_pixel(0.299f*a.x + 0.587f*b.x + 0.114f*c.x, sh);
            hist_pixel(0.299f*a.y + 0.587f*b.y + 0.114f*c.y, sh);
            hist_pixel(0.299f*a.z + 0.587f*b.z + 0.114f*c.z, sh);
            hist_pixel(0.299f*a.w + 0.587f*b.w + 0.114f*c.w, sh);
        }
        { unsigned int h = sh[t]; if (h) atomicAdd(&g_hist1[t], h); }
        __threadfence();
        __syncthreads();
        if (t == 0) {
            unsigned int old = atomicAdd(&g_done2, 1u);
            s_flag = (old == (unsigned)(G - 1)) ? 1u : 0u;
        }
        __syncthreads();
        if (s_flag != 0u) {
            __threadfence();
            compute_stats(g_hist1, false, t, s_wsum, s_cnt);
            if (t == 0) { __threadfence(); atomicAdd(&g_gen, 1u); }
        } else {
            if (t == 0) {
                while ((*(volatile unsigned int*)&g_gen) - g0 < 2u) __nanosleep(32);
            }
            __syncthreads();
        }
    }

    // ---- phase 2: apply affine + clamp (read + write full image) ----
    __threadfence();
    const float a  = __ldcg(&g_alpha);
    const float b  = __ldcg(&g_beta);
    const float hi = __ldcg(&g_hi);
    const int   id = __ldcg(&g_identity);

    const float4* pin  = (const float4*)img;
    float4*       pout = (float4*)out;
    for (int i = blockIdx.x * 256 + t; i < n4; i += stride) {
        float4 v = __ldcs(pin + i);
        float4 r;
        r.x = fminf(fmaxf(fmaf(v.x, a, b), 0.0f), hi);
        r.y = fminf(fmaxf(fmaf(v.y, a, b), 0.0f), hi);
        r.z = fminf(fmaxf(fmaf(v.z, a, b), 0.0f), hi);
        r.w = fminf(fmaxf(fmaf(v.w, a, b), 0.0f), hi);
        if (id) r = v;
        __stcs(pout + i, r);
    }
}

// ---------------- entry ----------------
extern "C" void kernel_launch(void* const* d_in, const int* in_sizes, int n_in,
                              void* d_out, int out_size)
{
    const float* img = (const float*)d_in[0];
    float* out = (float*)d_out;

    int n     = in_sizes[0];      // 3 * 4096 * 4096
    int npix  = n / 3;
    int npix4 = npix / 4;
    int n4    = n / 4;

    // Grid sized to GUARANTEED residency (software grid barrier must not
    // deadlock). These host queries enqueue no stream work -> capture-safe.
    int dev = 0;
    cudaGetDevice(&dev);
    int sms = 148;
    cudaDeviceGetAttribute(&sms, cudaDevAttrMultiProcessorCount, dev);
    int bpm = 0;
    cudaOccupancyMaxActiveBlocksPerMultiprocessor(&bpm, k_fused, 256, 0);
    if (bpm < 1) bpm = 1;
    int grid = sms * bpm;

    k_fused<<<grid, 256>>>(img, out, npix4, n4);
}